// round 6
// baseline (speedup 1.0000x reference)
#include <cuda_runtime.h>
#include <cstdint>

// Segment mean over sorted residue_index (int32).
// atom_features: [N_ATOMS, 128] float32
// residue_index: [N_ATOMS] int32 (sorted ascending)
// out:           [N_RES, 128] float32  (sum / max(count,1))

#define N_RES 250000
#define THREADS 256

__device__ int g_starts[N_RES + 1];

// Boundary scatter (vectorized: 4 atoms per thread via int4):
//  - for each boundary (ridx[i] != ridx[i-1]) fill starts[(prev, cur]] = i
//  - head: i == 0 uses prev = -1  (starts[0..ridx[0]] = 0)
//  - tail: last atom fills starts[last+1 .. N_RES] = n_atoms
__global__ void build_starts_kernel(const int* __restrict__ ridx, int n_atoms)
{
    int t = blockIdx.x * blockDim.x + threadIdx.x;
    int i0 = t * 4;
    if (i0 >= n_atoms) return;

    int c0, c1, c2, c3;
    if (i0 + 3 < n_atoms) {
        int4 c = *reinterpret_cast<const int4*>(ridx + i0);
        c0 = c.x; c1 = c.y; c2 = c.z; c3 = c.w;
    } else {
        c0 = ridx[i0];
        c1 = (i0 + 1 < n_atoms) ? ridx[i0 + 1] : c0;
        c2 = (i0 + 2 < n_atoms) ? ridx[i0 + 2] : c1;
        c3 = (i0 + 3 < n_atoms) ? ridx[i0 + 3] : c2;
    }

    int prev = (i0 == 0) ? -1 : __ldg(ridx + i0 - 1);

    int vals[4] = {c0, c1, c2, c3};
    #pragma unroll
    for (int j = 0; j < 4; ++j) {
        int i = i0 + j;
        if (i >= n_atoms) break;
        int cur = vals[j];
        if (cur != prev) {
            for (int q = prev + 1; q <= cur; ++q)
                g_starts[q] = i;
            prev = cur;
        }
        if (i == n_atoms - 1) {
            for (int q = cur + 1; q <= N_RES; ++q)
                g_starts[q] = n_atoms;
        }
    }
}

// One warp per residue: coalesced float4 row sums. Simple loop — measured
// fastest (R3: unrolled variant cost regs/occ and regressed; R4: this form
// hits 7.04 TB/s, 88.8% DRAM). DO NOT TOUCH without strong evidence.
__global__ void __launch_bounds__(THREADS)
residue_pool_kernel(const float4* __restrict__ feats,
                    float4* __restrict__ out)
{
    int warp_id = (blockIdx.x * THREADS + threadIdx.x) >> 5;
    int lane    = threadIdx.x & 31;
    if (warp_id >= N_RES) return;

    int start = g_starts[warp_id];
    int end   = g_starts[warp_id + 1];

    float4 acc = make_float4(0.f, 0.f, 0.f, 0.f);
    const float4* row = feats + (size_t)start * 32 + lane;
    for (int a = start; a < end; ++a, row += 32) {
        float4 v = __ldg(row);
        acc.x += v.x; acc.y += v.y; acc.z += v.z; acc.w += v.w;
    }

    int cnt = end - start;
    float inv = 1.0f / (float)(cnt > 0 ? cnt : 1);
    acc.x *= inv; acc.y *= inv; acc.z *= inv; acc.w *= inv;

    out[(size_t)warp_id * 32 + lane] = acc;
}

extern "C" void kernel_launch(void* const* d_in, const int* in_sizes, int n_in,
                              void* d_out, int out_size)
{
    const float4* feats = (const float4*)d_in[0];
    const int*    ridx  = (const int*)d_in[1];
    float4*       out   = (float4*)d_out;

    int n_atoms = in_sizes[1];

    int build_threads = (n_atoms + 3) / 4;
    build_starts_kernel<<<(build_threads + THREADS - 1) / THREADS, THREADS>>>(ridx, n_atoms);

    int total_threads = N_RES * 32;
    int blocks = (total_threads + THREADS - 1) / THREADS;
    residue_pool_kernel<<<blocks, THREADS>>>(feats, out);
}

// round 7
// speedup vs baseline: 1.0017x; 1.0017x over previous
#include <cuda_runtime.h>
#include <cstdint>

// Segment mean over sorted residue_index (int32).
// atom_features: [N_ATOMS, 128] float32
// residue_index: [N_ATOMS] int32 (sorted ascending)
// out:           [N_RES, 128] float32  (sum / max(count,1))

#define N_RES 250000
#define THREADS 256

__device__ int g_starts[N_RES + 1];

// Boundary scatter (vectorized: 4 atoms per thread via int4):
//  - for each boundary (ridx[i] != ridx[i-1]) fill starts[(prev, cur]] = i
//  - head: i == 0 uses prev = -1  (starts[0..ridx[0]] = 0)
//  - tail: last atom fills starts[last+1 .. N_RES] = n_atoms
__global__ void build_starts_kernel(const int* __restrict__ ridx, int n_atoms)
{
    int t = blockIdx.x * blockDim.x + threadIdx.x;
    int i0 = t * 4;
    if (i0 >= n_atoms) return;

    int c0, c1, c2, c3;
    if (i0 + 3 < n_atoms) {
        int4 c = *reinterpret_cast<const int4*>(ridx + i0);
        c0 = c.x; c1 = c.y; c2 = c.z; c3 = c.w;
    } else {
        c0 = ridx[i0];
        c1 = (i0 + 1 < n_atoms) ? ridx[i0 + 1] : c0;
        c2 = (i0 + 2 < n_atoms) ? ridx[i0 + 2] : c1;
        c3 = (i0 + 3 < n_atoms) ? ridx[i0 + 3] : c2;
    }

    int prev = (i0 == 0) ? -1 : __ldg(ridx + i0 - 1);

    int vals[4] = {c0, c1, c2, c3};
    #pragma unroll
    for (int j = 0; j < 4; ++j) {
        int i = i0 + j;
        if (i >= n_atoms) break;
        int cur = vals[j];
        if (cur != prev) {
            for (int q = prev + 1; q <= cur; ++q)
                g_starts[q] = i;
            prev = cur;
        }
        if (i == n_atoms - 1) {
            for (int q = cur + 1; q <= N_RES; ++q)
                g_starts[q] = n_atoms;
        }
    }
}

// One warp per residue: coalesced float4 row sums. Simple loop — measured
// fastest (R3: unrolled variant cost regs/occ and regressed; R4: this form
// hits 7.04 TB/s, 88.8% DRAM). DO NOT TOUCH without strong evidence.
__global__ void __launch_bounds__(THREADS)
residue_pool_kernel(const float4* __restrict__ feats,
                    float4* __restrict__ out)
{
    int warp_id = (blockIdx.x * THREADS + threadIdx.x) >> 5;
    int lane    = threadIdx.x & 31;
    if (warp_id >= N_RES) return;

    int start = g_starts[warp_id];
    int end   = g_starts[warp_id + 1];

    float4 acc = make_float4(0.f, 0.f, 0.f, 0.f);
    const float4* row = feats + (size_t)start * 32 + lane;
    for (int a = start; a < end; ++a, row += 32) {
        float4 v = __ldg(row);
        acc.x += v.x; acc.y += v.y; acc.z += v.z; acc.w += v.w;
    }

    int cnt = end - start;
    float inv = 1.0f / (float)(cnt > 0 ? cnt : 1);
    acc.x *= inv; acc.y *= inv; acc.z *= inv; acc.w *= inv;

    out[(size_t)warp_id * 32 + lane] = acc;
}

extern "C" void kernel_launch(void* const* d_in, const int* in_sizes, int n_in,
                              void* d_out, int out_size)
{
    const float4* feats = (const float4*)d_in[0];
    const int*    ridx  = (const int*)d_in[1];
    float4*       out   = (float4*)d_out;

    int n_atoms = in_sizes[1];

    int build_threads = (n_atoms + 3) / 4;
    build_starts_kernel<<<(build_threads + THREADS - 1) / THREADS, THREADS>>>(ridx, n_atoms);

    int total_threads = N_RES * 32;
    int blocks = (total_threads + THREADS - 1) / THREADS;
    residue_pool_kernel<<<blocks, THREADS>>>(feats, out);
}

// round 8
// speedup vs baseline: 1.0091x; 1.0074x over previous
#include <cuda_runtime.h>
#include <cstdint>

// Segment mean over sorted residue_index (int32).
// atom_features: [N_ATOMS, 128] float32
// residue_index: [N_ATOMS] int32 (sorted ascending)
// out:           [N_RES, 128] float32  (sum / max(count,1))

#define N_RES 250000
#define THREADS 256

__device__ int g_starts[N_RES + 1];

// Boundary scatter (vectorized: 4 atoms per thread via int4):
//  - for each boundary (ridx[i] != ridx[i-1]) fill starts[(prev, cur]] = i
//  - head: i == 0 uses prev = -1  (starts[0..ridx[0]] = 0)
//  - tail: last atom fills starts[last+1 .. N_RES] = n_atoms
__global__ void build_starts_kernel(const int* __restrict__ ridx, int n_atoms)
{
    int t = blockIdx.x * blockDim.x + threadIdx.x;
    int i0 = t * 4;
    if (i0 >= n_atoms) return;

    int c0, c1, c2, c3;
    if (i0 + 3 < n_atoms) {
        int4 c = *reinterpret_cast<const int4*>(ridx + i0);
        c0 = c.x; c1 = c.y; c2 = c.z; c3 = c.w;
    } else {
        c0 = ridx[i0];
        c1 = (i0 + 1 < n_atoms) ? ridx[i0 + 1] : c0;
        c2 = (i0 + 2 < n_atoms) ? ridx[i0 + 2] : c1;
        c3 = (i0 + 3 < n_atoms) ? ridx[i0 + 3] : c2;
    }

    int prev = (i0 == 0) ? -1 : __ldg(ridx + i0 - 1);

    int vals[4] = {c0, c1, c2, c3};
    #pragma unroll
    for (int j = 0; j < 4; ++j) {
        int i = i0 + j;
        if (i >= n_atoms) break;
        int cur = vals[j];
        if (cur != prev) {
            for (int q = prev + 1; q <= cur; ++q)
                g_starts[q] = i;
            prev = cur;
        }
        if (i == n_atoms - 1) {
            for (int q = cur + 1; q <= N_RES; ++q)
                g_starts[q] = n_atoms;
        }
    }
}

// One warp per residue: coalesced float4 row sums. Simple loop — measured
// fastest (R3: unrolled variant cost regs/occ and regressed; R4: this form
// hits 7.04 TB/s, 88.8% DRAM). DO NOT TOUCH without strong evidence.
__global__ void __launch_bounds__(THREADS)
residue_pool_kernel(const float4* __restrict__ feats,
                    float4* __restrict__ out)
{
    int warp_id = (blockIdx.x * THREADS + threadIdx.x) >> 5;
    int lane    = threadIdx.x & 31;
    if (warp_id >= N_RES) return;

    int start = g_starts[warp_id];
    int end   = g_starts[warp_id + 1];

    float4 acc = make_float4(0.f, 0.f, 0.f, 0.f);
    const float4* row = feats + (size_t)start * 32 + lane;
    for (int a = start; a < end; ++a, row += 32) {
        float4 v = __ldg(row);
        acc.x += v.x; acc.y += v.y; acc.z += v.z; acc.w += v.w;
    }

    int cnt = end - start;
    float inv = 1.0f / (float)(cnt > 0 ? cnt : 1);
    acc.x *= inv; acc.y *= inv; acc.z *= inv; acc.w *= inv;

    out[(size_t)warp_id * 32 + lane] = acc;
}

extern "C" void kernel_launch(void* const* d_in, const int* in_sizes, int n_in,
                              void* d_out, int out_size)
{
    const float4* feats = (const float4*)d_in[0];
    const int*    ridx  = (const int*)d_in[1];
    float4*       out   = (float4*)d_out;

    int n_atoms = in_sizes[1];

    int build_threads = (n_atoms + 3) / 4;
    build_starts_kernel<<<(build_threads + THREADS - 1) / THREADS, THREADS>>>(ridx, n_atoms);

    int total_threads = N_RES * 32;
    int blocks = (total_threads + THREADS - 1) / THREADS;
    residue_pool_kernel<<<blocks, THREADS>>>(feats, out);
}